// round 5
// baseline (speedup 1.0000x reference)
#include <cuda_runtime.h>
#include <math.h>

#define BB 128
#define SSN 256
#define TTN 256
#define UU 512
#define GG 2048
#define TI_T 257

__device__ float g_xproj[(size_t)TTN * BB * GG];
__device__ float g_h[(size_t)(TTN + 1) * BB * UU];
__device__ float g_c[(size_t)BB * UU];
__device__ float g_w[(size_t)TTN * BB * UU];
__device__ float g_zpart[(size_t)8 * BB * GG];

__global__ void init_kernel(const float* __restrict__ h0, const float* __restrict__ c0) {
    int i = blockIdx.x * blockDim.x + threadIdx.x;
    g_h[i] = h0[i];
    g_c[i] = c0[i];
}

// Packed f32x2 FMA (Blackwell): d.lo += a.lo*b.lo, d.hi += a.hi*b.hi
#define FMA2(d, a, b) asm("fma.rn.f32x2 %0, %1, %2, %3;" : "=l"(d) : "l"(a), "l"(b), "l"(d))
#define ULO(v) __uint_as_float((unsigned)(v))
#define UHI(v) __uint_as_float((unsigned)((v) >> 32))

// 128x128 GEMM tile, 256 threads, 8x8 microtile computed as 4 row-pairs x 8 cols
// via fma.rn.f32x2. A staged transposed [8][128]; B staged DUPLICATED [8][256]
// (sBd[k][2j]=sBd[k][2j+1]=B[k][j]) so b-operands are ready-made (b,b) pairs.
#define GEMM_DECLS \
    __shared__ float sA[8][128]; \
    __shared__ float sBd[8][256]; \
    const int tid = threadIdx.x; \
    const int ty = tid >> 4, tx = tid & 15; \
    const int arow = tid & 127, akf = tid >> 7; \
    const int bk = tid >> 5, bn4 = tid & 31; \
    unsigned long long acc[4][8]; \
    _Pragma("unroll") for (int pi = 0; pi < 4; pi++) \
    _Pragma("unroll") for (int j = 0; j < 8; j++) acc[pi][j] = 0ULL;

#define GEMM_STEP(AV, BV) { \
    float4 av = (AV); float4 bv = (BV); \
    __syncthreads(); \
    sA[akf*4+0][arow] = av.x; sA[akf*4+1][arow] = av.y; \
    sA[akf*4+2][arow] = av.z; sA[akf*4+3][arow] = av.w; \
    float* bd = &sBd[bk][bn4*8]; \
    ((float4*)bd)[0] = make_float4(bv.x, bv.x, bv.y, bv.y); \
    ((float4*)bd)[1] = make_float4(bv.z, bv.z, bv.w, bv.w); \
    __syncthreads(); \
    _Pragma("unroll") for (int kk = 0; kk < 8; kk++) { \
        const ulonglong2* pa = (const ulonglong2*)&sA[kk][ty*8]; \
        ulonglong2 pa0 = pa[0], pa1 = pa[1]; \
        unsigned long long ap[4] = {pa0.x, pa0.y, pa1.x, pa1.y}; \
        const ulonglong2* pb = (const ulonglong2*)&sBd[kk][tx*16]; \
        ulonglong2 pb0 = pb[0], pb1 = pb[1], pb2 = pb[2], pb3 = pb[3]; \
        unsigned long long bd8[8] = {pb0.x, pb0.y, pb1.x, pb1.y, pb2.x, pb2.y, pb3.x, pb3.y}; \
        _Pragma("unroll") for (int pi = 0; pi < 4; pi++) \
        _Pragma("unroll") for (int j = 0; j < 8; j++) FMA2(acc[pi][j], ap[pi], bd8[j]); \
    } }

__global__ __launch_bounds__(256) void xproj_kernel(const float* __restrict__ TI,
                                                    const float* __restrict__ W,
                                                    const float* __restrict__ bias) {
    GEMM_DECLS
    const int t = blockIdx.y, n0 = blockIdx.x * 128;
    const float* Ab = TI + (size_t)arow * (TI_T * UU) + (size_t)t * UU + akf * 4;
    const float* Bb = W + (size_t)bk * GG + n0 + bn4 * 4;
    for (int k0 = 0; k0 < UU; k0 += 8)
        GEMM_STEP(*(const float4*)(Ab + k0), *(const float4*)(Bb + (size_t)k0 * GG));
    float4 q0 = *(const float4*)&bias[n0 + tx*8];
    float4 q1 = *(const float4*)&bias[n0 + tx*8 + 4];
    float bb[8] = {q0.x,q0.y,q0.z,q0.w,q1.x,q1.y,q1.z,q1.w};
#pragma unroll
    for (int pi = 0; pi < 4; pi++) {
        float lo[8], hi[8];
#pragma unroll
        for (int j = 0; j < 8; j++) { lo[j] = ULO(acc[pi][j]) + bb[j]; hi[j] = UHI(acc[pi][j]) + bb[j]; }
        float* op0 = g_xproj + ((size_t)t * BB + ty*8 + 2*pi) * GG + n0 + tx*8;
        float* op1 = op0 + GG;
        *(float4*)op0     = make_float4(lo[0], lo[1], lo[2], lo[3]);
        *(float4*)(op0+4) = make_float4(lo[4], lo[5], lo[6], lo[7]);
        *(float4*)op1     = make_float4(hi[0], hi[1], hi[2], hi[3]);
        *(float4*)(op1+4) = make_float4(hi[4], hi[5], hi[6], hi[7]);
    }
}

__global__ __launch_bounds__(256) void step_gemm(const float* __restrict__ Rk, int t) {
    GEMM_DECLS
    const int gc0 = blockIdx.x * 128, split = blockIdx.y;
    const float* h = g_h + (size_t)t * (BB * UU);
    const int ks = split * 64;
    for (int k0 = ks; k0 < ks + 64; k0 += 8)
        GEMM_STEP(*(const float4*)(h + (size_t)arow*UU + k0 + akf*4),
                  *(const float4*)(Rk + (size_t)(k0+bk)*GG + gc0 + bn4*4));
    float* zp = g_zpart + (size_t)split * (BB * GG) + gc0;
#pragma unroll
    for (int pi = 0; pi < 4; pi++) {
        float* op0 = zp + (size_t)(ty*8 + 2*pi) * GG + tx*8;
        float* op1 = op0 + GG;
        *(float4*)op0     = make_float4(ULO(acc[pi][0]), ULO(acc[pi][1]), ULO(acc[pi][2]), ULO(acc[pi][3]));
        *(float4*)(op0+4) = make_float4(ULO(acc[pi][4]), ULO(acc[pi][5]), ULO(acc[pi][6]), ULO(acc[pi][7]));
        *(float4*)op1     = make_float4(UHI(acc[pi][0]), UHI(acc[pi][1]), UHI(acc[pi][2]), UHI(acc[pi][3]));
        *(float4*)(op1+4) = make_float4(UHI(acc[pi][4]), UHI(acc[pi][5]), UHI(acc[pi][6]), UHI(acc[pi][7]));
    }
}

__device__ __forceinline__ float sigm(float x) { return 1.f / (1.f + expf(-x)); }

// 16384 threads: thread handles (b, 4 consecutive u). All loads float4 + independent.
__global__ __launch_bounds__(128) void gate_kernel(int t) {
    int idx = blockIdx.x * 128 + threadIdx.x;
    int b = idx >> 7, uq = (idx & 127) << 2;
    const float* xp = g_xproj + (size_t)t * (BB * GG) + (size_t)b * GG;
    float4 zi = *(const float4*)(xp + uq);
    float4 zf = *(const float4*)(xp + 512 + uq);
    float4 zg = *(const float4*)(xp + 1024 + uq);
    float4 zo = *(const float4*)(xp + 1536 + uq);
#pragma unroll
    for (int s = 0; s < 8; s++) {
        const float* zp = g_zpart + (size_t)s * (BB * GG) + (size_t)b * GG;
        float4 a = *(const float4*)(zp + uq);
        float4 c = *(const float4*)(zp + 512 + uq);
        float4 d = *(const float4*)(zp + 1024 + uq);
        float4 e = *(const float4*)(zp + 1536 + uq);
        zi.x += a.x; zi.y += a.y; zi.z += a.z; zi.w += a.w;
        zf.x += c.x; zf.y += c.y; zf.z += c.z; zf.w += c.w;
        zg.x += d.x; zg.y += d.y; zg.z += d.z; zg.w += d.w;
        zo.x += e.x; zo.y += e.y; zo.z += e.z; zo.w += e.w;
    }
    float* cp = g_c + (size_t)b * UU + uq;
    float4 c = *(const float4*)cp;
    float4 cn, hn;
    cn.x = sigm(zf.x) * c.x + sigm(zi.x) * tanhf(zg.x);
    cn.y = sigm(zf.y) * c.y + sigm(zi.y) * tanhf(zg.y);
    cn.z = sigm(zf.z) * c.z + sigm(zi.z) * tanhf(zg.z);
    cn.w = sigm(zf.w) * c.w + sigm(zi.w) * tanhf(zg.w);
    hn.x = sigm(zo.x) * tanhf(cn.x);
    hn.y = sigm(zo.y) * tanhf(cn.y);
    hn.z = sigm(zo.z) * tanhf(cn.z);
    hn.w = sigm(zo.w) * tanhf(cn.w);
    *(float4*)cp = cn;
    *(float4*)&g_h[(size_t)(t+1) * (BB*UU) + (size_t)b * UU + uq] = hn;
}

// Attention: block = (16 timesteps, one batch b). smem: sHT[512][20] | sSc[16][264] | sS1[16][260]
#define HPAD 20
#define SCP 264
#define S1P 260
#define ATTN_SMEM_BYTES (18624 * 4)

__global__ __launch_bounds__(256) void attn_kernel(const float* __restrict__ SRC) {
    extern __shared__ float sm[];
    float* sHT = sm;
    float* sSc = sm + 10240;
    float* sS1 = sm + 14464;
    const int tid = threadIdx.x;
    const int t0 = blockIdx.x * 16, b = blockIdx.y;
    const float* src = SRC + (size_t)b * (SSN * UU);
#pragma unroll
    for (int i = 0; i < 8; i++) {
        int f4 = tid + i*256, tt = f4 >> 7, kq = f4 & 127;
        float4 v = *(const float4*)&g_h[(size_t)(t0+tt+1)*(BB*UU) + (size_t)b*UU + kq*4];
        sHT[(kq*4+0)*HPAD+tt] = v.x; sHT[(kq*4+1)*HPAD+tt] = v.y;
        sHT[(kq*4+2)*HPAD+tt] = v.z; sHT[(kq*4+3)*HPAD+tt] = v.w;
    }
    __syncthreads();
    const int tg = tid >> 6, sg = tid & 63;
    float acc[4][4];
#pragma unroll
    for (int i = 0; i < 4; i++)
#pragma unroll
        for (int j = 0; j < 4; j++) acc[i][j] = 0.f;
    for (int k0 = 0; k0 < UU; k0 += 16) {
#pragma unroll
        for (int i = 0; i < 4; i++) {
            int f4 = tid + i*256, s = f4 >> 2, kq = f4 & 3;
            float4 v = *(const float4*)&src[(size_t)s*UU + k0 + kq*4];
            sS1[(kq*4+0)*S1P+s] = v.x; sS1[(kq*4+1)*S1P+s] = v.y;
            sS1[(kq*4+2)*S1P+s] = v.z; sS1[(kq*4+3)*S1P+s] = v.w;
        }
        __syncthreads();
#pragma unroll
        for (int kk = 0; kk < 16; kk++) {
            float4 hv = *(const float4*)&sHT[(k0+kk)*HPAD + tg*4];
            float4 sv = *(const float4*)&sS1[kk*S1P + sg*4];
            float hr[4] = {hv.x,hv.y,hv.z,hv.w};
            float sr[4] = {sv.x,sv.y,sv.z,sv.w};
#pragma unroll
            for (int i = 0; i < 4; i++)
#pragma unroll
                for (int j = 0; j < 4; j++) acc[i][j] += hr[i]*sr[j];
        }
        __syncthreads();
    }
#pragma unroll
    for (int i = 0; i < 4; i++)
#pragma unroll
        for (int j = 0; j < 4; j++) sSc[(tg*4+i)*SCP + sg*4+j] = acc[i][j];
    __syncthreads();
    {
        const int w = tid >> 5, lane = tid & 31;
#pragma unroll
        for (int rr = 0; rr < 2; rr++) {
            int row = w*2 + rr;
            float v[8], m = -1e30f;
#pragma unroll
            for (int q = 0; q < 8; q++) { v[q] = sSc[row*SCP + lane + q*32]; m = fmaxf(m, v[q]); }
#pragma unroll
            for (int o = 16; o > 0; o >>= 1) m = fmaxf(m, __shfl_xor_sync(0xffffffffu, m, o));
            float ssum = 0.f;
#pragma unroll
            for (int q = 0; q < 8; q++) { v[q] = expf(v[q] - m); ssum += v[q]; }
#pragma unroll
            for (int o = 16; o > 0; o >>= 1) ssum += __shfl_xor_sync(0xffffffffu, ssum, o);
            float inv = 1.f / ssum;
#pragma unroll
            for (int q = 0; q < 8; q++) sSc[row*SCP + lane + q*32] = v[q] * inv;
        }
    }
    __syncthreads();
    float* sSrc = sm;
    const int ug = tid & 63;
    float acc2[4][8];
#pragma unroll
    for (int i = 0; i < 4; i++)
#pragma unroll
        for (int j = 0; j < 8; j++) acc2[i][j] = 0.f;
    for (int s0 = 0; s0 < SSN; s0 += 16) {
        __syncthreads();
#pragma unroll
        for (int i = 0; i < 8; i++) {
            int f4 = tid + i*256, si = f4 >> 7, uq = f4 & 127;
            *(float4*)&sSrc[si*UU + uq*4] = *(const float4*)&src[(size_t)(s0+si)*UU + uq*4];
        }
        __syncthreads();
#pragma unroll
        for (int si = 0; si < 16; si++) {
            float ar[4];
#pragma unroll
            for (int i = 0; i < 4; i++) ar[i] = sSc[(tg*4+i)*SCP + s0 + si];
            float4 u0 = *(const float4*)&sSrc[si*UU + ug*8];
            float4 u1 = *(const float4*)&sSrc[si*UU + ug*8 + 4];
            float ur[8] = {u0.x,u0.y,u0.z,u0.w,u1.x,u1.y,u1.z,u1.w};
#pragma unroll
            for (int i = 0; i < 4; i++)
#pragma unroll
                for (int j = 0; j < 8; j++) acc2[i][j] += ar[i]*ur[j];
        }
    }
#pragma unroll
    for (int i = 0; i < 4; i++) {
        float* wp = g_w + ((size_t)(t0 + tg*4 + i) * BB + b) * UU + ug*8;
        *(float4*)wp     = make_float4(acc2[i][0], acc2[i][1], acc2[i][2], acc2[i][3]);
        *(float4*)(wp+4) = make_float4(acc2[i][4], acc2[i][5], acc2[i][6], acc2[i][7]);
    }
}

__global__ __launch_bounds__(256) void final_gemm(const float* __restrict__ Wa,
                                                  float* __restrict__ out) {
    GEMM_DECLS
    const int t = blockIdx.y, n0 = blockIdx.x * 128;
    for (int k0 = 0; k0 < 1024; k0 += 8) {
        const float* Ab = (k0 < 512)
            ? (g_h + (size_t)(t+1)*(BB*UU) + k0)
            : (g_w + (size_t)t*(BB*UU) + (k0 - 512));
        GEMM_STEP(*(const float4*)(Ab + (size_t)arow*UU + akf*4),
                  *(const float4*)(Wa + (size_t)(k0+bk)*UU + n0 + bn4*4));
    }
#pragma unroll
    for (int pi = 0; pi < 4; pi++) {
        float* op0 = out + (size_t)(ty*8 + 2*pi) * (TTN*UU) + (size_t)t * UU + n0 + tx*8;
        float* op1 = op0 + (size_t)(TTN*UU);
        *(float4*)op0     = make_float4(tanhf(ULO(acc[pi][0])), tanhf(ULO(acc[pi][1])), tanhf(ULO(acc[pi][2])), tanhf(ULO(acc[pi][3])));
        *(float4*)(op0+4) = make_float4(tanhf(ULO(acc[pi][4])), tanhf(ULO(acc[pi][5])), tanhf(ULO(acc[pi][6])), tanhf(ULO(acc[pi][7])));
        *(float4*)op1     = make_float4(tanhf(UHI(acc[pi][0])), tanhf(UHI(acc[pi][1])), tanhf(UHI(acc[pi][2])), tanhf(UHI(acc[pi][3])));
        *(float4*)(op1+4) = make_float4(tanhf(UHI(acc[pi][4])), tanhf(UHI(acc[pi][5])), tanhf(UHI(acc[pi][6])), tanhf(UHI(acc[pi][7])));
    }
}

extern "C" void kernel_launch(void* const* d_in, const int* in_sizes, int n_in,
                              void* d_out, int out_size) {
    (void)in_sizes; (void)n_in; (void)out_size;
    const float* h0   = (const float*)d_in[0];
    const float* c0   = (const float*)d_in[1];
    const float* src  = (const float*)d_in[2];
    const float* ti   = (const float*)d_in[3];
    const float* W    = (const float*)d_in[4];
    const float* Rk   = (const float*)d_in[5];
    const float* bias = (const float*)d_in[6];
    const float* Wa   = (const float*)d_in[7];
    float* out = (float*)d_out;

    cudaFuncSetAttribute(attn_kernel, cudaFuncAttributeMaxDynamicSharedMemorySize,
                         ATTN_SMEM_BYTES);

    init_kernel<<<256, 256>>>(h0, c0);
    xproj_kernel<<<dim3(16, 256), 256>>>(ti, W, bias);
    for (int t = 0; t < TTN; t++) {
        step_gemm<<<dim3(16, 8), 256>>>(Rk, t);
        gate_kernel<<<128, 128>>>(t);
    }
    attn_kernel<<<dim3(16, 128), 256, ATTN_SMEM_BYTES>>>(src);
    final_gemm<<<dim3(4, 256), 256>>>(Wa, out);
}

// round 6
// speedup vs baseline: 2.0245x; 2.0245x over previous
#include <cuda_runtime.h>
#include <math.h>

#define BB 128
#define SSN 256
#define TTN 256
#define UU 512
#define GG 2048
#define TI_T 257

__device__ float g_xproj[(size_t)TTN * BB * GG];
__device__ float g_h[(size_t)(TTN + 1) * BB * UU];
__device__ float g_c[(size_t)BB * UU];
__device__ float g_w[(size_t)TTN * BB * UU];
__device__ float g_zpart[(size_t)8 * BB * GG];
__device__ volatile unsigned g_flags[128];
__device__ volatile unsigned g_phase;

__global__ void init_kernel(const float* __restrict__ h0, const float* __restrict__ c0) {
    int i = blockIdx.x * blockDim.x + threadIdx.x;
    g_h[i] = h0[i];
    g_c[i] = c0[i];
    if (blockIdx.x == 0) {
        if (threadIdx.x < 128) g_flags[threadIdx.x] = 0;
        if (threadIdx.x == 128) g_phase = 0;
    }
}

// 128x128 GEMM tile pieces: smem/id decls, acc decls, one K=8 step (R4-proven form).
#define GEMM_SMEM_DECLS \
    __shared__ float sA[8][128]; \
    __shared__ float sB[8][128]; \
    const int tid = threadIdx.x; \
    const int ty = tid >> 4, tx = tid & 15; \
    const int arow = tid & 127, akf = tid >> 7; \
    const int bk = tid >> 5, bn4 = tid & 31;

#define GEMM_ACC_DECLS \
    float acc[8][8]; \
    _Pragma("unroll") for (int i = 0; i < 8; i++) \
    _Pragma("unroll") for (int j = 0; j < 8; j++) acc[i][j] = 0.f;

#define GEMM_STEP(AV, BV) { \
    float4 av = (AV); float4 bv = (BV); \
    __syncthreads(); \
    sA[akf*4+0][arow] = av.x; sA[akf*4+1][arow] = av.y; \
    sA[akf*4+2][arow] = av.z; sA[akf*4+3][arow] = av.w; \
    *(float4*)&sB[bk][bn4*4] = bv; \
    __syncthreads(); \
    _Pragma("unroll") for (int kk = 0; kk < 8; kk++) { \
        float4 a0 = *(const float4*)&sA[kk][ty*8]; \
        float4 a1 = *(const float4*)&sA[kk][ty*8+4]; \
        float4 b0 = *(const float4*)&sB[kk][tx*8]; \
        float4 b1 = *(const float4*)&sB[kk][tx*8+4]; \
        float ar[8] = {a0.x,a0.y,a0.z,a0.w,a1.x,a1.y,a1.z,a1.w}; \
        float br[8] = {b0.x,b0.y,b0.z,b0.w,b1.x,b1.y,b1.z,b1.w}; \
        _Pragma("unroll") for (int i = 0; i < 8; i++) \
        _Pragma("unroll") for (int j = 0; j < 8; j++) acc[i][j] += ar[i]*br[j]; \
    } }

__global__ __launch_bounds__(256) void xproj_kernel(const float* __restrict__ TI,
                                                    const float* __restrict__ W,
                                                    const float* __restrict__ bias) {
    GEMM_SMEM_DECLS
    GEMM_ACC_DECLS
    const int t = blockIdx.y, n0 = blockIdx.x * 128;
    const float* Ab = TI + (size_t)arow * (TI_T * UU) + (size_t)t * UU + akf * 4;
    const float* Bb = W + (size_t)bk * GG + n0 + bn4 * 4;
    for (int k0 = 0; k0 < UU; k0 += 8)
        GEMM_STEP(*(const float4*)(Ab + k0), *(const float4*)(Bb + (size_t)k0 * GG));
    float4 q0 = *(const float4*)&bias[n0 + tx*8];
    float4 q1 = *(const float4*)&bias[n0 + tx*8 + 4];
    float bb[8] = {q0.x,q0.y,q0.z,q0.w,q1.x,q1.y,q1.z,q1.w};
#pragma unroll
    for (int i = 0; i < 8; i++) {
        float* op = g_xproj + ((size_t)t * BB + ty*8 + i) * GG + n0 + tx*8;
        *(float4*)op     = make_float4(acc[i][0]+bb[0], acc[i][1]+bb[1], acc[i][2]+bb[2], acc[i][3]+bb[3]);
        *(float4*)(op+4) = make_float4(acc[i][4]+bb[4], acc[i][5]+bb[5], acc[i][6]+bb[6], acc[i][7]+bb[7]);
    }
}

__device__ __forceinline__ float sigm(float x) { return 1.f / (1.f + expf(-x)); }

// Grid barrier: per-block flag + block0 aggregation + phase broadcast.
__device__ __forceinline__ void grid_barrier(unsigned gen) {
    __syncthreads();
    if (threadIdx.x == 0) {
        __threadfence();
        g_flags[blockIdx.x] = gen;
    }
    if (blockIdx.x == 0) {
        bool done = false;
        do {
            bool ok = (threadIdx.x < 128) ? (g_flags[threadIdx.x] >= gen) : true;
            done = __syncthreads_and(ok);
        } while (!done);
        if (threadIdx.x == 0) { __threadfence(); g_phase = gen; }
    } else {
        if (threadIdx.x == 0) {
            while (g_phase < gen) { }
            __threadfence();
        }
        __syncthreads();
    }
}

// Persistent recurrence: 128 blocks x 256 threads, co-resident (<=148 SMs).
// Per step: phase A = split-K GEMM (16 col-tiles x 8 K-splits) -> g_zpart;
// barrier; phase B = gate update (reads xproj + 8 partials, same sum order
// as the R4 gate kernel -> bitwise-identical); barrier.
__global__ __launch_bounds__(256) void recurrence_kernel(const float* __restrict__ Rk) {
    GEMM_SMEM_DECLS
    const int ct = blockIdx.x & 15, split = blockIdx.x >> 4;
    const int gc0 = ct * 128;
    const int ks = split * 64;
    // phase-B mapping: thread -> (b, 2 consecutive u)
    const int gidx = blockIdx.x * 256 + tid;
    const int gb = gidx >> 8, gu = (gidx & 255) << 1;
    unsigned gen = 0;

    for (int t = 0; t < TTN; t++) {
        // ---- phase A: z partial GEMM ----
        {
            GEMM_ACC_DECLS
            const float* h = g_h + (size_t)t * (BB * UU);
            for (int k0 = ks; k0 < ks + 64; k0 += 8)
                GEMM_STEP(__ldcg((const float4*)(h + (size_t)arow*UU + k0 + akf*4)),
                          *(const float4*)(Rk + (size_t)(k0+bk)*GG + gc0 + bn4*4));
            float* zp = g_zpart + (size_t)split * (BB * GG) + gc0;
#pragma unroll
            for (int i = 0; i < 8; i++) {
                float* op = zp + (size_t)(ty*8 + i) * GG + tx*8;
                *(float4*)op     = make_float4(acc[i][0], acc[i][1], acc[i][2], acc[i][3]);
                *(float4*)(op+4) = make_float4(acc[i][4], acc[i][5], acc[i][6], acc[i][7]);
            }
        }
        grid_barrier(++gen);
        // ---- phase B: gates ----
        {
            const float* xp = g_xproj + (size_t)t * (BB * GG) + (size_t)gb * GG + gu;
            float2 zi = *(const float2*)(xp);
            float2 zf = *(const float2*)(xp + 512);
            float2 zg = *(const float2*)(xp + 1024);
            float2 zo = *(const float2*)(xp + 1536);
#pragma unroll
            for (int s = 0; s < 8; s++) {
                const float* zp = g_zpart + (size_t)s * (BB * GG) + (size_t)gb * GG + gu;
                float2 a = __ldcg((const float2*)(zp));
                float2 f = __ldcg((const float2*)(zp + 512));
                float2 g = __ldcg((const float2*)(zp + 1024));
                float2 o = __ldcg((const float2*)(zp + 1536));
                zi.x += a.x; zi.y += a.y;
                zf.x += f.x; zf.y += f.y;
                zg.x += g.x; zg.y += g.y;
                zo.x += o.x; zo.y += o.y;
            }
            float* cp = g_c + (size_t)gb * UU + gu;
            float2 c = *(const float2*)cp;
            float2 cn, hn;
            cn.x = sigm(zf.x) * c.x + sigm(zi.x) * tanhf(zg.x);
            cn.y = sigm(zf.y) * c.y + sigm(zi.y) * tanhf(zg.y);
            hn.x = sigm(zo.x) * tanhf(cn.x);
            hn.y = sigm(zo.y) * tanhf(cn.y);
            *(float2*)cp = cn;
            *(float2*)&g_h[(size_t)(t+1) * (BB*UU) + (size_t)gb * UU + gu] = hn;
        }
        grid_barrier(++gen);
    }
}

// Attention: block = (16 timesteps, one batch b). smem: sHT[512][20] | sSc[16][264] | sS1[16][260]
#define HPAD 20
#define SCP 264
#define S1P 260
#define ATTN_SMEM_BYTES (18624 * 4)

__global__ __launch_bounds__(256) void attn_kernel(const float* __restrict__ SRC) {
    extern __shared__ float sm[];
    float* sHT = sm;
    float* sSc = sm + 10240;
    float* sS1 = sm + 14464;
    const int tid = threadIdx.x;
    const int t0 = blockIdx.x * 16, b = blockIdx.y;
    const float* src = SRC + (size_t)b * (SSN * UU);
#pragma unroll
    for (int i = 0; i < 8; i++) {
        int f4 = tid + i*256, tt = f4 >> 7, kq = f4 & 127;
        float4 v = *(const float4*)&g_h[(size_t)(t0+tt+1)*(BB*UU) + (size_t)b*UU + kq*4];
        sHT[(kq*4+0)*HPAD+tt] = v.x; sHT[(kq*4+1)*HPAD+tt] = v.y;
        sHT[(kq*4+2)*HPAD+tt] = v.z; sHT[(kq*4+3)*HPAD+tt] = v.w;
    }
    __syncthreads();
    const int tg = tid >> 6, sg = tid & 63;
    float acc[4][4];
#pragma unroll
    for (int i = 0; i < 4; i++)
#pragma unroll
        for (int j = 0; j < 4; j++) acc[i][j] = 0.f;
    for (int k0 = 0; k0 < UU; k0 += 16) {
#pragma unroll
        for (int i = 0; i < 4; i++) {
            int f4 = tid + i*256, s = f4 >> 2, kq = f4 & 3;
            float4 v = *(const float4*)&src[(size_t)s*UU + k0 + kq*4];
            sS1[(kq*4+0)*S1P+s] = v.x; sS1[(kq*4+1)*S1P+s] = v.y;
            sS1[(kq*4+2)*S1P+s] = v.z; sS1[(kq*4+3)*S1P+s] = v.w;
        }
        __syncthreads();
#pragma unroll
        for (int kk = 0; kk < 16; kk++) {
            float4 hv = *(const float4*)&sHT[(k0+kk)*HPAD + tg*4];
            float4 sv = *(const float4*)&sS1[kk*S1P + sg*4];
            float hr[4] = {hv.x,hv.y,hv.z,hv.w};
            float sr[4] = {sv.x,sv.y,sv.z,sv.w};
#pragma unroll
            for (int i = 0; i < 4; i++)
#pragma unroll
                for (int j = 0; j < 4; j++) acc[i][j] += hr[i]*sr[j];
        }
        __syncthreads();
    }
#pragma unroll
    for (int i = 0; i < 4; i++)
#pragma unroll
        for (int j = 0; j < 4; j++) sSc[(tg*4+i)*SCP + sg*4+j] = acc[i][j];
    __syncthreads();
    {
        const int w = tid >> 5, lane = tid & 31;
#pragma unroll
        for (int rr = 0; rr < 2; rr++) {
            int row = w*2 + rr;
            float v[8], m = -1e30f;
#pragma unroll
            for (int q = 0; q < 8; q++) { v[q] = sSc[row*SCP + lane + q*32]; m = fmaxf(m, v[q]); }
#pragma unroll
            for (int o = 16; o > 0; o >>= 1) m = fmaxf(m, __shfl_xor_sync(0xffffffffu, m, o));
            float ssum = 0.f;
#pragma unroll
            for (int q = 0; q < 8; q++) { v[q] = expf(v[q] - m); ssum += v[q]; }
#pragma unroll
            for (int o = 16; o > 0; o >>= 1) ssum += __shfl_xor_sync(0xffffffffu, ssum, o);
            float inv = 1.f / ssum;
#pragma unroll
            for (int q = 0; q < 8; q++) sSc[row*SCP + lane + q*32] = v[q] * inv;
        }
    }
    __syncthreads();
    float* sSrc = sm;
    const int ug = tid & 63;
    float acc2[4][8];
#pragma unroll
    for (int i = 0; i < 4; i++)
#pragma unroll
        for (int j = 0; j < 8; j++) acc2[i][j] = 0.f;
    for (int s0 = 0; s0 < SSN; s0 += 16) {
        __syncthreads();
#pragma unroll
        for (int i = 0; i < 8; i++) {
            int f4 = tid + i*256, si = f4 >> 7, uq = f4 & 127;
            *(float4*)&sSrc[si*UU + uq*4] = *(const float4*)&src[(size_t)(s0+si)*UU + uq*4];
        }
        __syncthreads();
#pragma unroll
        for (int si = 0; si < 16; si++) {
            float ar[4];
#pragma unroll
            for (int i = 0; i < 4; i++) ar[i] = sSc[(tg*4+i)*SCP + s0 + si];
            float4 u0 = *(const float4*)&sSrc[si*UU + ug*8];
            float4 u1 = *(const float4*)&sSrc[si*UU + ug*8 + 4];
            float ur[8] = {u0.x,u0.y,u0.z,u0.w,u1.x,u1.y,u1.z,u1.w};
#pragma unroll
            for (int i = 0; i < 4; i++)
#pragma unroll
                for (int j = 0; j < 8; j++) acc2[i][j] += ar[i]*ur[j];
        }
    }
#pragma unroll
    for (int i = 0; i < 4; i++) {
        float* wp = g_w + ((size_t)(t0 + tg*4 + i) * BB + b) * UU + ug*8;
        *(float4*)wp     = make_float4(acc2[i][0], acc2[i][1], acc2[i][2], acc2[i][3]);
        *(float4*)(wp+4) = make_float4(acc2[i][4], acc2[i][5], acc2[i][6], acc2[i][7]);
    }
}

__global__ __launch_bounds__(256) void final_gemm(const float* __restrict__ Wa,
                                                  float* __restrict__ out) {
    GEMM_SMEM_DECLS
    GEMM_ACC_DECLS
    const int t = blockIdx.y, n0 = blockIdx.x * 128;
    for (int k0 = 0; k0 < 1024; k0 += 8) {
        const float* Ab = (k0 < 512)
            ? (g_h + (size_t)(t+1)*(BB*UU) + k0)
            : (g_w + (size_t)t*(BB*UU) + (k0 - 512));
        GEMM_STEP(*(const float4*)(Ab + (size_t)arow*UU + akf*4),
                  *(const float4*)(Wa + (size_t)(k0+bk)*UU + n0 + bn4*4));
    }
#pragma unroll
    for (int i = 0; i < 8; i++) {
        int r = ty*8 + i;
        float* op = out + (size_t)r * (TTN*UU) + (size_t)t * UU + n0 + tx*8;
        *(float4*)op     = make_float4(tanhf(acc[i][0]), tanhf(acc[i][1]), tanhf(acc[i][2]), tanhf(acc[i][3]));
        *(float4*)(op+4) = make_float4(tanhf(acc[i][4]), tanhf(acc[i][5]), tanhf(acc[i][6]), tanhf(acc[i][7]));
    }
}

extern "C" void kernel_launch(void* const* d_in, const int* in_sizes, int n_in,
                              void* d_out, int out_size) {
    (void)in_sizes; (void)n_in; (void)out_size;
    const float* h0   = (const float*)d_in[0];
    const float* c0   = (const float*)d_in[1];
    const float* src  = (const float*)d_in[2];
    const float* ti   = (const float*)d_in[3];
    const float* W    = (const float*)d_in[4];
    const float* Rk   = (const float*)d_in[5];
    const float* bias = (const float*)d_in[6];
    const float* Wa   = (const float*)d_in[7];
    float* out = (float*)d_out;

    cudaFuncSetAttribute(attn_kernel, cudaFuncAttributeMaxDynamicSharedMemorySize,
                         ATTN_SMEM_BYTES);

    init_kernel<<<256, 256>>>(h0, c0);
    xproj_kernel<<<dim3(16, 256), 256>>>(ti, W, bias);
    recurrence_kernel<<<128, 256>>>(Rk);
    attn_kernel<<<dim3(16, 128), 256, ATTN_SMEM_BYTES>>>(src);
    final_gemm<<<dim3(4, 256), 256>>>(Wa, out);
}

// round 7
// speedup vs baseline: 2.9762x; 1.4701x over previous
#include <cuda_runtime.h>
#include <cuda_bf16.h>
#include <mma.h>
#include <math.h>
using namespace nvcuda;

#define BB 128
#define SSN 256
#define TTN 256
#define UU 512
#define GG 2048
#define TI_T 257
#define BU (BB * UU)

typedef __nv_bfloat16 bf16;

__device__ float g_xproj[(size_t)TTN * BB * GG];      // raw GEMM (bias folded into gates)
__device__ float g_h[(size_t)(TTN + 1) * BU];
__device__ float g_c[(size_t)BU];
__device__ float g_zpart[(size_t)8 * BB * GG];
__device__ bf16 g_hbh[(size_t)(TTN + 1) * BU], g_hbl[(size_t)(TTN + 1) * BU];
__device__ bf16 g_wbh[(size_t)TTN * BU], g_wbl[(size_t)TTN * BU];
__device__ bf16 g_tih[(size_t)TTN * BU], g_til[(size_t)TTN * BU];
__device__ bf16 g_wkh[(size_t)UU * GG], g_wkl[(size_t)UU * GG];
__device__ bf16 g_rkh[(size_t)UU * GG], g_rkl[(size_t)UU * GG];
__device__ bf16 g_wah[(size_t)2 * UU * UU], g_wal[(size_t)2 * UU * UU];
__device__ volatile unsigned g_flags[128];
__device__ volatile unsigned g_phase;

__device__ __forceinline__ void split2(float x, bf16& h, bf16& l) {
    h = __float2bfloat16(x);
    l = __float2bfloat16(x - __bfloat162float(h));
}

__global__ void init_kernel(const float* __restrict__ h0, const float* __restrict__ c0) {
    int i = blockIdx.x * blockDim.x + threadIdx.x;
    float v = h0[i];
    g_h[i] = v;
    split2(v, g_hbh[i], g_hbl[i]);
    g_c[i] = c0[i];
    if (blockIdx.x == 0) {
        if (threadIdx.x < 128) g_flags[threadIdx.x] = 0;
        if (threadIdx.x == 128) g_phase = 0;
    }
}

__global__ void cvt_kernel(const float* __restrict__ src, bf16* __restrict__ hi, bf16* __restrict__ lo) {
    int i = blockIdx.x * 256 + threadIdx.x;
    split2(src[i], hi[i], lo[i]);
}

// target_inputs [b][TI_T][u] -> [t][b][u] bf16 hi/lo, t < TTN
__global__ void cvt_ti_kernel(const float* __restrict__ ti) {
    int i = blockIdx.x * 256 + threadIdx.x;
    int u = i & 511, b = (i >> 9) & 127, t = i >> 16;
    float x = ti[(size_t)b * (TI_T * UU) + (size_t)t * UU + u];
    split2(x, g_tih[i], g_til[i]);
}

// ---------------- WMMA 128x128 tile machinery: 8 warps (2x4), warp 64x32 ------
#define WMMA_DECLS \
    const int tid = threadIdx.x; \
    const int wid = tid >> 5; \
    const int wm = (wid >> 2) * 64, wn = (wid & 3) * 32; \
    wmma::fragment<wmma::accumulator, 16, 16, 16, float> facc[4][2]; \
    _Pragma("unroll") for (int i = 0; i < 4; i++) \
    _Pragma("unroll") for (int j = 0; j < 2; j++) wmma::fill_fragment(facc[i][j], 0.f);

#define WMMA_SMEM \
    __shared__ bf16 sAh[128][24], sAl[128][24]; \
    __shared__ bf16 sBh[16][136], sBl[16][136];

// stage one K=16 chunk: A rows=128 (thread: row=tid>>1, 8 cols), B rows=16 x 128 cols
#define STAGE(AH, AL, ASTRIDE, BH, BL, BSTRIDE) { \
    __syncthreads(); \
    int r = tid >> 1, c8 = (tid & 1) * 8; \
    *(uint4*)&sAh[r][c8] = *(const uint4*)((AH) + (size_t)r * (ASTRIDE) + c8); \
    *(uint4*)&sAl[r][c8] = *(const uint4*)((AL) + (size_t)r * (ASTRIDE) + c8); \
    int kr = tid >> 4, nc8 = (tid & 15) * 8; \
    *(uint4*)&sBh[kr][nc8] = *(const uint4*)((BH) + (size_t)kr * (BSTRIDE) + nc8); \
    *(uint4*)&sBl[kr][nc8] = *(const uint4*)((BL) + (size_t)kr * (BSTRIDE) + nc8); \
    __syncthreads(); }

#define WMMA_CHUNK { \
    wmma::fragment<wmma::matrix_a, 16, 16, 16, bf16, wmma::row_major> ah[4], al[4]; \
    wmma::fragment<wmma::matrix_b, 16, 16, 16, bf16, wmma::row_major> bh[2], bl[2]; \
    _Pragma("unroll") for (int i = 0; i < 4; i++) { \
        wmma::load_matrix_sync(ah[i], &sAh[wm + i * 16][0], 24); \
        wmma::load_matrix_sync(al[i], &sAl[wm + i * 16][0], 24); } \
    _Pragma("unroll") for (int j = 0; j < 2; j++) { \
        wmma::load_matrix_sync(bh[j], &sBh[0][wn + j * 16], 136); \
        wmma::load_matrix_sync(bl[j], &sBl[0][wn + j * 16], 136); } \
    _Pragma("unroll") for (int i = 0; i < 4; i++) \
    _Pragma("unroll") for (int j = 0; j < 2; j++) { \
        wmma::mma_sync(facc[i][j], ah[i], bh[j], facc[i][j]); \
        wmma::mma_sync(facc[i][j], ah[i], bl[j], facc[i][j]); \
        wmma::mma_sync(facc[i][j], al[i], bh[j], facc[i][j]); } }

#define WMMA_STORE(BASE, LD) \
    _Pragma("unroll") for (int i = 0; i < 4; i++) \
    _Pragma("unroll") for (int j = 0; j < 2; j++) \
        wmma::store_matrix_sync((BASE) + (size_t)(wm + i * 16) * (LD) + wn + j * 16, \
                                facc[i][j], (LD), wmma::mem_row_major);

// x_proj[t] = TI_bf16[t] @ W_bf16  (raw; bias added in gate phase)
__global__ __launch_bounds__(256) void xproj_kernel() {
    WMMA_SMEM
    WMMA_DECLS
    const int t = blockIdx.y, n0 = blockIdx.x * 128;
    const bf16* Ah = g_tih + (size_t)t * BU;
    const bf16* Al = g_til + (size_t)t * BU;
    for (int k0 = 0; k0 < UU; k0 += 16) {
        STAGE(Ah + k0, Al + k0, UU,
              g_wkh + (size_t)k0 * GG + n0, g_wkl + (size_t)k0 * GG + n0, GG)
        WMMA_CHUNK
    }
    WMMA_STORE(g_xproj + (size_t)t * (BB * GG) + n0, GG)
}

__device__ __forceinline__ float sigm(float x) { return 1.f / (1.f + expf(-x)); }

__device__ __forceinline__ void grid_barrier(unsigned gen) {
    __syncthreads();
    if (threadIdx.x == 0) {
        __threadfence();
        g_flags[blockIdx.x] = gen;
    }
    if (blockIdx.x == 0) {
        bool done = false;
        do {
            bool ok = (threadIdx.x < 128) ? (g_flags[threadIdx.x] >= gen) : true;
            done = __syncthreads_and(ok);
        } while (!done);
        if (threadIdx.x == 0) { __threadfence(); g_phase = gen; }
    } else {
        if (threadIdx.x == 0) {
            while (g_phase < gen) { }
            __threadfence();
        }
        __syncthreads();
    }
}

// Persistent recurrence: 128 blocks. Phase A: z = h_bf16 @ R_bf16 split-K (16 ct x 8 split).
// Phase B: gates (+bias), writes h fp32 + bf16 hi/lo.
__global__ __launch_bounds__(256) void recurrence_kernel(const float* __restrict__ bias) {
    WMMA_SMEM
    const int tid = threadIdx.x;
    const int wid = tid >> 5;
    const int wm = (wid >> 2) * 64, wn = (wid & 3) * 32;
    const int ct = blockIdx.x & 15, split = blockIdx.x >> 4;
    const int gc0 = ct * 128, ks = split * 64;
    // phase-B mapping: (b, 2 consecutive u); bias preloaded (u fixed across t)
    const int gidx = blockIdx.x * 256 + tid;
    const int gb = gidx >> 8, gu = (gidx & 255) << 1;
    const float2 bi = *(const float2*)(bias + gu);
    const float2 bfg = *(const float2*)(bias + 512 + gu);
    const float2 bg = *(const float2*)(bias + 1024 + gu);
    const float2 bo = *(const float2*)(bias + 1536 + gu);
    unsigned gen = 0;

    for (int t = 0; t < TTN; t++) {
        {   // phase A
            wmma::fragment<wmma::accumulator, 16, 16, 16, float> facc[4][2];
#pragma unroll
            for (int i = 0; i < 4; i++)
#pragma unroll
                for (int j = 0; j < 2; j++) wmma::fill_fragment(facc[i][j], 0.f);
            const bf16* Ah = g_hbh + (size_t)t * BU;
            const bf16* Al = g_hbl + (size_t)t * BU;
            for (int k0 = ks; k0 < ks + 64; k0 += 16) {
                STAGE(Ah + k0, Al + k0, UU,
                      g_rkh + (size_t)k0 * GG + gc0, g_rkl + (size_t)k0 * GG + gc0, GG)
                WMMA_CHUNK
            }
            WMMA_STORE(g_zpart + (size_t)split * (BB * GG) + gc0, GG)
        }
        grid_barrier(++gen);
        {   // phase B
            const float* xp = g_xproj + (size_t)t * (BB * GG) + (size_t)gb * GG + gu;
            float2 zi = *(const float2*)(xp);
            float2 zf = *(const float2*)(xp + 512);
            float2 zg = *(const float2*)(xp + 1024);
            float2 zo = *(const float2*)(xp + 1536);
#pragma unroll
            for (int s = 0; s < 8; s++) {
                const float* zp = g_zpart + (size_t)s * (BB * GG) + (size_t)gb * GG + gu;
                float2 a = __ldcg((const float2*)(zp));
                float2 f = __ldcg((const float2*)(zp + 512));
                float2 g = __ldcg((const float2*)(zp + 1024));
                float2 o = __ldcg((const float2*)(zp + 1536));
                zi.x += a.x; zi.y += a.y;
                zf.x += f.x; zf.y += f.y;
                zg.x += g.x; zg.y += g.y;
                zo.x += o.x; zo.y += o.y;
            }
            zi.x += bi.x; zi.y += bi.y;
            zf.x += bfg.x; zf.y += bfg.y;
            zg.x += bg.x; zg.y += bg.y;
            zo.x += bo.x; zo.y += bo.y;
            float* cp = g_c + (size_t)gb * UU + gu;
            float2 c = *(const float2*)cp;
            float2 cn, hn;
            cn.x = sigm(zf.x) * c.x + sigm(zi.x) * tanhf(zg.x);
            cn.y = sigm(zf.y) * c.y + sigm(zi.y) * tanhf(zg.y);
            hn.x = sigm(zo.x) * tanhf(cn.x);
            hn.y = sigm(zo.y) * tanhf(cn.y);
            *(float2*)cp = cn;
            size_t hidx = (size_t)(t + 1) * BU + (size_t)gb * UU + gu;
            *(float2*)&g_h[hidx] = hn;
            split2(hn.x, g_hbh[hidx], g_hbl[hidx]);
            split2(hn.y, g_hbh[hidx + 1], g_hbl[hidx + 1]);
        }
        grid_barrier(++gen);
    }
}

// Attention (fp32): block = (16 timesteps, one batch). Writes context as bf16 hi/lo.
#define HPAD 20
#define SCP 264
#define S1P 260
#define ATTN_SMEM_BYTES (18624 * 4)

__global__ __launch_bounds__(256) void attn_kernel(const float* __restrict__ SRC) {
    extern __shared__ float sm[];
    float* sHT = sm;
    float* sSc = sm + 10240;
    float* sS1 = sm + 14464;
    const int tid = threadIdx.x;
    const int t0 = blockIdx.x * 16, b = blockIdx.y;
    const float* src = SRC + (size_t)b * (SSN * UU);
#pragma unroll
    for (int i = 0; i < 8; i++) {
        int f4 = tid + i*256, tt = f4 >> 7, kq = f4 & 127;
        float4 v = *(const float4*)&g_h[(size_t)(t0+tt+1)*BU + (size_t)b*UU + kq*4];
        sHT[(kq*4+0)*HPAD+tt] = v.x; sHT[(kq*4+1)*HPAD+tt] = v.y;
        sHT[(kq*4+2)*HPAD+tt] = v.z; sHT[(kq*4+3)*HPAD+tt] = v.w;
    }
    __syncthreads();
    const int tg = tid >> 6, sg = tid & 63;
    float acc[4][4];
#pragma unroll
    for (int i = 0; i < 4; i++)
#pragma unroll
        for (int j = 0; j < 4; j++) acc[i][j] = 0.f;
    for (int k0 = 0; k0 < UU; k0 += 16) {
#pragma unroll
        for (int i = 0; i < 4; i++) {
            int f4 = tid + i*256, s = f4 >> 2, kq = f4 & 3;
            float4 v = *(const float4*)&src[(size_t)s*UU + k0 + kq*4];
            sS1[(kq*4+0)*S1P+s] = v.x; sS1[(kq*4+1)*S1P+s] = v.y;
            sS1[(kq*4+2)*S1P+s] = v.z; sS1[(kq*4+3)*S1P+s] = v.w;
        }
        __syncthreads();
#pragma unroll
        for (int kk = 0; kk < 16; kk++) {
            float4 hv = *(const float4*)&sHT[(k0+kk)*HPAD + tg*4];
            float4 sv = *(const float4*)&sS1[kk*S1P + sg*4];
            float hr[4] = {hv.x,hv.y,hv.z,hv.w};
            float sr[4] = {sv.x,sv.y,sv.z,sv.w};
#pragma unroll
            for (int i = 0; i < 4; i++)
#pragma unroll
                for (int j = 0; j < 4; j++) acc[i][j] += hr[i]*sr[j];
        }
        __syncthreads();
    }
#pragma unroll
    for (int i = 0; i < 4; i++)
#pragma unroll
        for (int j = 0; j < 4; j++) sSc[(tg*4+i)*SCP + sg*4+j] = acc[i][j];
    __syncthreads();
    {
        const int w = tid >> 5, lane = tid & 31;
#pragma unroll
        for (int rr = 0; rr < 2; rr++) {
            int row = w*2 + rr;
            float v[8], m = -1e30f;
#pragma unroll
            for (int q = 0; q < 8; q++) { v[q] = sSc[row*SCP + lane + q*32]; m = fmaxf(m, v[q]); }
#pragma unroll
            for (int o = 16; o > 0; o >>= 1) m = fmaxf(m, __shfl_xor_sync(0xffffffffu, m, o));
            float ssum = 0.f;
#pragma unroll
            for (int q = 0; q < 8; q++) { v[q] = expf(v[q] - m); ssum += v[q]; }
#pragma unroll
            for (int o = 16; o > 0; o >>= 1) ssum += __shfl_xor_sync(0xffffffffu, ssum, o);
            float inv = 1.f / ssum;
#pragma unroll
            for (int q = 0; q < 8; q++) sSc[row*SCP + lane + q*32] = v[q] * inv;
        }
    }
    __syncthreads();
    float* sSrc = sm;
    const int ug = tid & 63;
    float acc2[4][8];
#pragma unroll
    for (int i = 0; i < 4; i++)
#pragma unroll
        for (int j = 0; j < 8; j++) acc2[i][j] = 0.f;
    for (int s0 = 0; s0 < SSN; s0 += 16) {
        __syncthreads();
#pragma unroll
        for (int i = 0; i < 8; i++) {
            int f4 = tid + i*256, si = f4 >> 7, uq = f4 & 127;
            *(float4*)&sSrc[si*UU + uq*4] = *(const float4*)&src[(size_t)(s0+si)*UU + uq*4];
        }
        __syncthreads();
#pragma unroll
        for (int si = 0; si < 16; si++) {
            float ar[4];
#pragma unroll
            for (int i = 0; i < 4; i++) ar[i] = sSc[(tg*4+i)*SCP + s0 + si];
            float4 u0 = *(const float4*)&sSrc[si*UU + ug*8];
            float4 u1 = *(const float4*)&sSrc[si*UU + ug*8 + 4];
            float ur[8] = {u0.x,u0.y,u0.z,u0.w,u1.x,u1.y,u1.z,u1.w};
#pragma unroll
            for (int i = 0; i < 4; i++)
#pragma unroll
                for (int j = 0; j < 8; j++) acc2[i][j] += ar[i]*ur[j];
        }
    }
#pragma unroll
    for (int i = 0; i < 4; i++) {
        size_t base = ((size_t)(t0 + tg*4 + i) * BB + b) * UU + ug*8;
#pragma unroll
        for (int j = 0; j < 8; j++)
            split2(acc2[i][j], g_wbh[base + j], g_wbl[base + j]);
    }
}

// out_raw[b][t][n] = [h_t ; w_t] @ Wa  (bf16-split), tanh applied by tanh_kernel
__global__ __launch_bounds__(256) void final_gemm(float* __restrict__ out) {
    WMMA_SMEM
    WMMA_DECLS
    const int t = blockIdx.y, n0 = blockIdx.x * 128;
    for (int k0 = 0; k0 < 1024; k0 += 16) {
        const bf16* Ah;
        const bf16* Al;
        int kc;
        if (k0 < 512) { Ah = g_hbh + (size_t)(t+1) * BU; Al = g_hbl + (size_t)(t+1) * BU; kc = k0; }
        else          { Ah = g_wbh + (size_t)t * BU;     Al = g_wbl + (size_t)t * BU;     kc = k0 - 512; }
        STAGE(Ah + kc, Al + kc, UU,
              g_wah + (size_t)k0 * UU + n0, g_wal + (size_t)k0 * UU + n0, UU)
        WMMA_CHUNK
    }
    WMMA_STORE(out + (size_t)t * UU + n0, (size_t)(TTN * UU))
}

__global__ void tanh_kernel(float* __restrict__ out) {
    int i = blockIdx.x * 256 + threadIdx.x;
    float4 v = ((float4*)out)[i];
    v.x = tanhf(v.x); v.y = tanhf(v.y); v.z = tanhf(v.z); v.w = tanhf(v.w);
    ((float4*)out)[i] = v;
}

extern "C" void kernel_launch(void* const* d_in, const int* in_sizes, int n_in,
                              void* d_out, int out_size) {
    (void)in_sizes; (void)n_in; (void)out_size;
    const float* h0   = (const float*)d_in[0];
    const float* c0   = (const float*)d_in[1];
    const float* src  = (const float*)d_in[2];
    const float* ti   = (const float*)d_in[3];
    const float* W    = (const float*)d_in[4];
    const float* Rk   = (const float*)d_in[5];
    const float* bias = (const float*)d_in[6];
    const float* Wa   = (const float*)d_in[7];
    float* out = (float*)d_out;

    cudaFuncSetAttribute(attn_kernel, cudaFuncAttributeMaxDynamicSharedMemorySize,
                         ATTN_SMEM_BYTES);

    init_kernel<<<256, 256>>>(h0, c0);
    // weight / input conversions (bf16 hi/lo)
    bf16 *wkh, *wkl, *rkh, *rkl, *wah, *wal;
    cudaGetSymbolAddress((void**)&wkh, g_wkh); cudaGetSymbolAddress((void**)&wkl, g_wkl);
    cudaGetSymbolAddress((void**)&rkh, g_rkh); cudaGetSymbolAddress((void**)&rkl, g_rkl);
    cudaGetSymbolAddress((void**)&wah, g_wah); cudaGetSymbolAddress((void**)&wal, g_wal);
    cvt_kernel<<<4096, 256>>>(W, wkh, wkl);
    cvt_kernel<<<4096, 256>>>(Rk, rkh, rkl);
    cvt_kernel<<<2048, 256>>>(Wa, wah, wal);
    cvt_ti_kernel<<<65536, 256>>>(ti);

    xproj_kernel<<<dim3(16, 256), 256>>>();
    recurrence_kernel<<<128, 256>>>(bias);
    attn_kernel<<<dim3(16, 128), 256, ATTN_SMEM_BYTES>>>(src);
    final_gemm<<<dim3(4, 256), 256>>>(out);
    tanh_kernel<<<16384, 256>>>(out);
}

// round 8
// speedup vs baseline: 3.2614x; 1.0958x over previous
#include <cuda_runtime.h>
#include <cuda_bf16.h>
#include <mma.h>
#include <math.h>
using namespace nvcuda;

#define BB 128
#define SSN 256
#define TTN 256
#define UU 512
#define GG 2048
#define TI_T 257
#define BU (BB * UU)

typedef __nv_bfloat16 bf16;

__device__ float g_xproj[(size_t)TTN * BB * GG];
__device__ float g_h[(size_t)(TTN + 1) * BU];
__device__ float g_c[(size_t)BU];
__device__ float g_zpart[(size_t)8 * BB * GG];
__device__ bf16 g_hbh[(size_t)(TTN + 1) * BU], g_hbl[(size_t)(TTN + 1) * BU];
__device__ bf16 g_wbh[(size_t)TTN * BU], g_wbl[(size_t)TTN * BU];
__device__ bf16 g_tih[(size_t)TTN * BU], g_til[(size_t)TTN * BU];
__device__ bf16 g_wkh[(size_t)UU * GG], g_wkl[(size_t)UU * GG];
__device__ bf16 g_rkh[(size_t)UU * GG], g_rkl[(size_t)UU * GG];
__device__ bf16 g_wah[(size_t)2 * UU * UU], g_wal[(size_t)2 * UU * UU];
__device__ volatile unsigned g_flags[128];
__device__ volatile unsigned g_phase;

__device__ __forceinline__ void split2(float x, bf16& h, bf16& l) {
    h = __float2bfloat16(x);
    l = __float2bfloat16(x - __bfloat162float(h));
}

__global__ void init_kernel(const float* __restrict__ h0, const float* __restrict__ c0) {
    int i = blockIdx.x * blockDim.x + threadIdx.x;
    float v = h0[i];
    g_h[i] = v;
    split2(v, g_hbh[i], g_hbl[i]);
    g_c[i] = c0[i];
    if (blockIdx.x == 0) {
        if (threadIdx.x < 128) g_flags[threadIdx.x] = 0;
        if (threadIdx.x == 128) g_phase = 0;
    }
}

__global__ void cvt_kernel(const float* __restrict__ src, bf16* __restrict__ hi, bf16* __restrict__ lo) {
    int i = blockIdx.x * 256 + threadIdx.x;
    split2(src[i], hi[i], lo[i]);
}

__global__ void cvt_ti_kernel(const float* __restrict__ ti) {
    int i = blockIdx.x * 256 + threadIdx.x;
    int u = i & 511, b = (i >> 9) & 127, t = i >> 16;
    float x = ti[(size_t)b * (TI_T * UU) + (size_t)t * UU + u];
    split2(x, g_tih[i], g_til[i]);
}

// ---------------- WMMA 128x128 tile machinery (one-shot GEMMs) ----------------
#define WMMA_DECLS \
    const int tid = threadIdx.x; \
    const int wid = tid >> 5; \
    const int wm = (wid >> 2) * 64, wn = (wid & 3) * 32; \
    wmma::fragment<wmma::accumulator, 16, 16, 16, float> facc[4][2]; \
    _Pragma("unroll") for (int i = 0; i < 4; i++) \
    _Pragma("unroll") for (int j = 0; j < 2; j++) wmma::fill_fragment(facc[i][j], 0.f);

#define WMMA_SMEM \
    __shared__ bf16 sAh[128][24], sAl[128][24]; \
    __shared__ bf16 sBh[16][136], sBl[16][136];

#define STAGE(AH, AL, ASTRIDE, BH, BL, BSTRIDE) { \
    __syncthreads(); \
    int r = tid >> 1, c8 = (tid & 1) * 8; \
    *(uint4*)&sAh[r][c8] = *(const uint4*)((AH) + (size_t)r * (ASTRIDE) + c8); \
    *(uint4*)&sAl[r][c8] = *(const uint4*)((AL) + (size_t)r * (ASTRIDE) + c8); \
    int kr = tid >> 4, nc8 = (tid & 15) * 8; \
    *(uint4*)&sBh[kr][nc8] = *(const uint4*)((BH) + (size_t)kr * (BSTRIDE) + nc8); \
    *(uint4*)&sBl[kr][nc8] = *(const uint4*)((BL) + (size_t)kr * (BSTRIDE) + nc8); \
    __syncthreads(); }

#define WMMA_CHUNK { \
    wmma::fragment<wmma::matrix_a, 16, 16, 16, bf16, wmma::row_major> ah[4], al[4]; \
    wmma::fragment<wmma::matrix_b, 16, 16, 16, bf16, wmma::row_major> bh[2], bl[2]; \
    _Pragma("unroll") for (int i = 0; i < 4; i++) { \
        wmma::load_matrix_sync(ah[i], &sAh[wm + i * 16][0], 24); \
        wmma::load_matrix_sync(al[i], &sAl[wm + i * 16][0], 24); } \
    _Pragma("unroll") for (int j = 0; j < 2; j++) { \
        wmma::load_matrix_sync(bh[j], &sBh[0][wn + j * 16], 136); \
        wmma::load_matrix_sync(bl[j], &sBl[0][wn + j * 16], 136); } \
    _Pragma("unroll") for (int i = 0; i < 4; i++) \
    _Pragma("unroll") for (int j = 0; j < 2; j++) { \
        wmma::mma_sync(facc[i][j], ah[i], bh[j], facc[i][j]); \
        wmma::mma_sync(facc[i][j], ah[i], bl[j], facc[i][j]); \
        wmma::mma_sync(facc[i][j], al[i], bh[j], facc[i][j]); } }

#define WMMA_STORE(BASE, LD) \
    _Pragma("unroll") for (int i = 0; i < 4; i++) \
    _Pragma("unroll") for (int j = 0; j < 2; j++) \
        wmma::store_matrix_sync((BASE) + (size_t)(wm + i * 16) * (LD) + wn + j * 16, \
                                facc[i][j], (LD), wmma::mem_row_major);

__global__ __launch_bounds__(256) void xproj_kernel() {
    WMMA_SMEM
    WMMA_DECLS
    const int t = blockIdx.y, n0 = blockIdx.x * 128;
    const bf16* Ah = g_tih + (size_t)t * BU;
    const bf16* Al = g_til + (size_t)t * BU;
    for (int k0 = 0; k0 < UU; k0 += 16) {
        STAGE(Ah + k0, Al + k0, UU,
              g_wkh + (size_t)k0 * GG + n0, g_wkl + (size_t)k0 * GG + n0, GG)
        WMMA_CHUNK
    }
    WMMA_STORE(g_xproj + (size_t)t * (BB * GG) + n0, GG)
}

__device__ __forceinline__ float sigm(float x) { return 1.f / (1.f + expf(-x)); }

__device__ __forceinline__ void grid_barrier(unsigned gen) {
    __syncthreads();
    if (threadIdx.x == 0) {
        __threadfence();
        g_flags[blockIdx.x] = gen;
    }
    if (blockIdx.x == 0) {
        bool done = false;
        do {
            bool ok = (threadIdx.x < 128) ? (g_flags[threadIdx.x] >= gen) : true;
            done = __syncthreads_and(ok);
        } while (!done);
        if (threadIdx.x == 0) { __threadfence(); g_phase = gen; }
    } else {
        if (threadIdx.x == 0) {
            while (g_phase < gen) { }
            __threadfence();
        }
        __syncthreads();
    }
}

// Persistent recurrence, R-resident smem.
// Dyn smem (bf16 elems): sAh[128][72] @0, sAl @9216, sRh[64][136] @18432, sRl @27136.
#define REC_SMEM_BYTES ((18432 + 2 * 64 * 136) * 2)   // 71680 B

__global__ __launch_bounds__(256) void recurrence_kernel(const float* __restrict__ bias) {
    extern __shared__ bf16 rs[];
    bf16* sAh = rs;
    bf16* sAl = rs + 9216;
    bf16* sRh = rs + 18432;
    bf16* sRl = rs + 27136;
    const int tid = threadIdx.x;
    const int wid = tid >> 5;
    const int wm = (wid >> 2) * 64, wn = (wid & 3) * 32;
    const int ct = blockIdx.x & 15, split = blockIdx.x >> 4;
    const int gc0 = ct * 128, ks = split * 64;

    // Load this block's R tile (64K x 128N, hi+lo) once.
#pragma unroll
    for (int i = 0; i < 4; i++) {
        int idx = tid + i * 256;
        int kr = idx >> 4, c8 = (idx & 15) * 8;
        *(uint4*)&sRh[kr * 136 + c8] = *(const uint4*)&g_rkh[(size_t)(ks + kr) * GG + gc0 + c8];
        *(uint4*)&sRl[kr * 136 + c8] = *(const uint4*)&g_rkl[(size_t)(ks + kr) * GG + gc0 + c8];
    }

    // phase-B mapping: (b, 2 consecutive u); bias preloaded
    const int gidx = blockIdx.x * 256 + tid;
    const int gb = gidx >> 8, gu = (gidx & 255) << 1;
    const float2 bi = *(const float2*)(bias + gu);
    const float2 bfg = *(const float2*)(bias + 512 + gu);
    const float2 bg = *(const float2*)(bias + 1024 + gu);
    const float2 bo = *(const float2*)(bias + 1536 + gu);
    unsigned gen = 0;

    for (int t = 0; t < TTN; t++) {
        // ---- phase A: stage h tile, MMA against resident R ----
        __syncthreads();   // t=0: R loaded; t>0: prior-step frag reads done
        {
            const bf16* Ah = g_hbh + (size_t)t * BU + ks;
            const bf16* Al = g_hbl + (size_t)t * BU + ks;
#pragma unroll
            for (int i = 0; i < 4; i++) {
                int idx = tid + i * 256;
                int r = idx >> 3, c8 = (idx & 7) * 8;
                *(uint4*)&sAh[r * 72 + c8] = *(const uint4*)(Ah + (size_t)r * UU + c8);
                *(uint4*)&sAl[r * 72 + c8] = *(const uint4*)(Al + (size_t)r * UU + c8);
            }
        }
        __syncthreads();
        {
            wmma::fragment<wmma::accumulator, 16, 16, 16, float> facc[4][2];
#pragma unroll
            for (int i = 0; i < 4; i++)
#pragma unroll
                for (int j = 0; j < 2; j++) wmma::fill_fragment(facc[i][j], 0.f);
#pragma unroll
            for (int kc = 0; kc < 4; kc++) {
                wmma::fragment<wmma::matrix_a, 16, 16, 16, bf16, wmma::row_major> ah[4], al[4];
                wmma::fragment<wmma::matrix_b, 16, 16, 16, bf16, wmma::row_major> bh[2], bl[2];
#pragma unroll
                for (int i = 0; i < 4; i++) {
                    wmma::load_matrix_sync(ah[i], &sAh[(wm + i * 16) * 72 + kc * 16], 72);
                    wmma::load_matrix_sync(al[i], &sAl[(wm + i * 16) * 72 + kc * 16], 72);
                }
#pragma unroll
                for (int j = 0; j < 2; j++) {
                    wmma::load_matrix_sync(bh[j], &sRh[(kc * 16) * 136 + wn + j * 16], 136);
                    wmma::load_matrix_sync(bl[j], &sRl[(kc * 16) * 136 + wn + j * 16], 136);
                }
#pragma unroll
                for (int i = 0; i < 4; i++)
#pragma unroll
                    for (int j = 0; j < 2; j++) {
                        wmma::mma_sync(facc[i][j], ah[i], bh[j], facc[i][j]);
                        wmma::mma_sync(facc[i][j], ah[i], bl[j], facc[i][j]);
                        wmma::mma_sync(facc[i][j], al[i], bh[j], facc[i][j]);
                    }
            }
            float* zbase = g_zpart + (size_t)split * (BB * GG) + gc0;
#pragma unroll
            for (int i = 0; i < 4; i++)
#pragma unroll
                for (int j = 0; j < 2; j++)
                    wmma::store_matrix_sync(zbase + (size_t)(wm + i * 16) * GG + wn + j * 16,
                                            facc[i][j], GG, wmma::mem_row_major);
        }
        grid_barrier(++gen);
        // ---- phase B: gates ----
        {
            const float* xp = g_xproj + (size_t)t * (BB * GG) + (size_t)gb * GG + gu;
            float2 zi = *(const float2*)(xp);
            float2 zf = *(const float2*)(xp + 512);
            float2 zg = *(const float2*)(xp + 1024);
            float2 zo = *(const float2*)(xp + 1536);
#pragma unroll
            for (int s = 0; s < 8; s++) {
                const float* zp = g_zpart + (size_t)s * (BB * GG) + (size_t)gb * GG + gu;
                float2 a = __ldcg((const float2*)(zp));
                float2 f = __ldcg((const float2*)(zp + 512));
                float2 g = __ldcg((const float2*)(zp + 1024));
                float2 o = __ldcg((const float2*)(zp + 1536));
                zi.x += a.x; zi.y += a.y;
                zf.x += f.x; zf.y += f.y;
                zg.x += g.x; zg.y += g.y;
                zo.x += o.x; zo.y += o.y;
            }
            zi.x += bi.x; zi.y += bi.y;
            zf.x += bfg.x; zf.y += bfg.y;
            zg.x += bg.x; zg.y += bg.y;
            zo.x += bo.x; zo.y += bo.y;
            float* cp = g_c + (size_t)gb * UU + gu;
            float2 c = *(const float2*)cp;
            float2 cn, hn;
            cn.x = sigm(zf.x) * c.x + sigm(zi.x) * tanhf(zg.x);
            cn.y = sigm(zf.y) * c.y + sigm(zi.y) * tanhf(zg.y);
            hn.x = sigm(zo.x) * tanhf(cn.x);
            hn.y = sigm(zo.y) * tanhf(cn.y);
            *(float2*)cp = cn;
            size_t hidx = (size_t)(t + 1) * BU + (size_t)gb * UU + gu;
            *(float2*)&g_h[hidx] = hn;
            split2(hn.x, g_hbh[hidx], g_hbl[hidx]);
            split2(hn.y, g_hbh[hidx + 1], g_hbl[hidx + 1]);
        }
        grid_barrier(++gen);
    }
}

// Attention (fp32): block = (16 timesteps, one batch). Writes context as bf16 hi/lo.
#define HPAD 20
#define SCP 264
#define S1P 260
#define ATTN_SMEM_BYTES (18624 * 4)

__global__ __launch_bounds__(256) void attn_kernel(const float* __restrict__ SRC) {
    extern __shared__ float sm[];
    float* sHT = sm;
    float* sSc = sm + 10240;
    float* sS1 = sm + 14464;
    const int tid = threadIdx.x;
    const int t0 = blockIdx.x * 16, b = blockIdx.y;
    const float* src = SRC + (size_t)b * (SSN * UU);
#pragma unroll
    for (int i = 0; i < 8; i++) {
        int f4 = tid + i*256, tt = f4 >> 7, kq = f4 & 127;
        float4 v = *(const float4*)&g_h[(size_t)(t0+tt+1)*BU + (size_t)b*UU + kq*4];
        sHT[(kq*4+0)*HPAD+tt] = v.x; sHT[(kq*4+1)*HPAD+tt] = v.y;
        sHT[(kq*4+2)*HPAD+tt] = v.z; sHT[(kq*4+3)*HPAD+tt] = v.w;
    }
    __syncthreads();
    const int tg = tid >> 6, sg = tid & 63;
    float acc[4][4];
#pragma unroll
    for (int i = 0; i < 4; i++)
#pragma unroll
        for (int j = 0; j < 4; j++) acc[i][j] = 0.f;
    for (int k0 = 0; k0 < UU; k0 += 16) {
#pragma unroll
        for (int i = 0; i < 4; i++) {
            int f4 = tid + i*256, s = f4 >> 2, kq = f4 & 3;
            float4 v = *(const float4*)&src[(size_t)s*UU + k0 + kq*4];
            sS1[(kq*4+0)*S1P+s] = v.x; sS1[(kq*4+1)*S1P+s] = v.y;
            sS1[(kq*4+2)*S1P+s] = v.z; sS1[(kq*4+3)*S1P+s] = v.w;
        }
        __syncthreads();
#pragma unroll
        for (int kk = 0; kk < 16; kk++) {
            float4 hv = *(const float4*)&sHT[(k0+kk)*HPAD + tg*4];
            float4 sv = *(const float4*)&sS1[kk*S1P + sg*4];
            float hr[4] = {hv.x,hv.y,hv.z,hv.w};
            float sr[4] = {sv.x,sv.y,sv.z,sv.w};
#pragma unroll
            for (int i = 0; i < 4; i++)
#pragma unroll
                for (int j = 0; j < 4; j++) acc[i][j] += hr[i]*sr[j];
        }
        __syncthreads();
    }
#pragma unroll
    for (int i = 0; i < 4; i++)
#pragma unroll
        for (int j = 0; j < 4; j++) sSc[(tg*4+i)*SCP + sg*4+j] = acc[i][j];
    __syncthreads();
    {
        const int w = tid >> 5, lane = tid & 31;
#pragma unroll
        for (int rr = 0; rr < 2; rr++) {
            int row = w*2 + rr;
            float v[8], m = -1e30f;
#pragma unroll
            for (int q = 0; q < 8; q++) { v[q] = sSc[row*SCP + lane + q*32]; m = fmaxf(m, v[q]); }
#pragma unroll
            for (int o = 16; o > 0; o >>= 1) m = fmaxf(m, __shfl_xor_sync(0xffffffffu, m, o));
            float ssum = 0.f;
#pragma unroll
            for (int q = 0; q < 8; q++) { v[q] = expf(v[q] - m); ssum += v[q]; }
#pragma unroll
            for (int o = 16; o > 0; o >>= 1) ssum += __shfl_xor_sync(0xffffffffu, ssum, o);
            float inv = 1.f / ssum;
#pragma unroll
            for (int q = 0; q < 8; q++) sSc[row*SCP + lane + q*32] = v[q] * inv;
        }
    }
    __syncthreads();
    float* sSrc = sm;
    const int ug = tid & 63;
    float acc2[4][8];
#pragma unroll
    for (int i = 0; i < 4; i++)
#pragma unroll
        for (int j = 0; j < 8; j++) acc2[i][j] = 0.f;
    for (int s0 = 0; s0 < SSN; s0 += 16) {
        __syncthreads();
#pragma unroll
        for (int i = 0; i < 8; i++) {
            int f4 = tid + i*256, si = f4 >> 7, uq = f4 & 127;
            *(float4*)&sSrc[si*UU + uq*4] = *(const float4*)&src[(size_t)(s0+si)*UU + uq*4];
        }
        __syncthreads();
#pragma unroll
        for (int si = 0; si < 16; si++) {
            float ar[4];
#pragma unroll
            for (int i = 0; i < 4; i++) ar[i] = sSc[(tg*4+i)*SCP + s0 + si];
            float4 u0 = *(const float4*)&sSrc[si*UU + ug*8];
            float4 u1 = *(const float4*)&sSrc[si*UU + ug*8 + 4];
            float ur[8] = {u0.x,u0.y,u0.z,u0.w,u1.x,u1.y,u1.z,u1.w};
#pragma unroll
            for (int i = 0; i < 4; i++)
#pragma unroll
                for (int j = 0; j < 8; j++) acc2[i][j] += ar[i]*ur[j];
        }
    }
#pragma unroll
    for (int i = 0; i < 4; i++) {
        size_t base = ((size_t)(t0 + tg*4 + i) * BB + b) * UU + ug*8;
#pragma unroll
        for (int j = 0; j < 8; j++)
            split2(acc2[i][j], g_wbh[base + j], g_wbl[base + j]);
    }
}

__global__ __launch_bounds__(256) void final_gemm(float* __restrict__ out) {
    WMMA_SMEM
    WMMA_DECLS
    const int t = blockIdx.y, n0 = blockIdx.x * 128;
    for (int k0 = 0; k0 < 1024; k0 += 16) {
        const bf16* Ah;
        const bf16* Al;
        int kc;
        if (k0 < 512) { Ah = g_hbh + (size_t)(t+1) * BU; Al = g_hbl + (size_t)(t+1) * BU; kc = k0; }
        else          { Ah = g_wbh + (size_t)t * BU;     Al = g_wbl + (size_t)t * BU;     kc = k0 - 512; }
        STAGE(Ah + kc, Al + kc, UU,
              g_wah + (size_t)k0 * UU + n0, g_wal + (size_t)k0 * UU + n0, UU)
        WMMA_CHUNK
    }
    WMMA_STORE(out + (size_t)t * UU + n0, (size_t)(TTN * UU))
}

__global__ void tanh_kernel(float* __restrict__ out) {
    int i = blockIdx.x * 256 + threadIdx.x;
    float4 v = ((float4*)out)[i];
    v.x = tanhf(v.x); v.y = tanhf(v.y); v.z = tanhf(v.z); v.w = tanhf(v.w);
    ((float4*)out)[i] = v;
}

extern "C" void kernel_launch(void* const* d_in, const int* in_sizes, int n_in,
                              void* d_out, int out_size) {
    (void)in_sizes; (void)n_in; (void)out_size;
    const float* h0   = (const float*)d_in[0];
    const float* c0   = (const float*)d_in[1];
    const float* src  = (const float*)d_in[2];
    const float* ti   = (const float*)d_in[3];
    const float* W    = (const float*)d_in[4];
    const float* Rk   = (const float*)d_in[5];
    const float* bias = (const float*)d_in[6];
    const float* Wa   = (const float*)d_in[7];
    float* out = (float*)d_out;

    cudaFuncSetAttribute(attn_kernel, cudaFuncAttributeMaxDynamicSharedMemorySize,
                         ATTN_SMEM_BYTES);
    cudaFuncSetAttribute(recurrence_kernel, cudaFuncAttributeMaxDynamicSharedMemorySize,
                         REC_SMEM_BYTES);

    init_kernel<<<256, 256>>>(h0, c0);
    bf16 *wkh, *wkl, *rkh, *rkl, *wah, *wal;
    cudaGetSymbolAddress((void**)&wkh, g_wkh); cudaGetSymbolAddress((void**)&wkl, g_wkl);
    cudaGetSymbolAddress((void**)&rkh, g_rkh); cudaGetSymbolAddress((void**)&rkl, g_rkl);
    cudaGetSymbolAddress((void**)&wah, g_wah); cudaGetSymbolAddress((void**)&wal, g_wal);
    cvt_kernel<<<4096, 256>>>(W, wkh, wkl);
    cvt_kernel<<<4096, 256>>>(Rk, rkh, rkl);
    cvt_kernel<<<2048, 256>>>(Wa, wah, wal);
    cvt_ti_kernel<<<65536, 256>>>(ti);

    xproj_kernel<<<dim3(16, 256), 256>>>();
    recurrence_kernel<<<128, 256, REC_SMEM_BYTES>>>(bias);
    attn_kernel<<<dim3(16, 128), 256, ATTN_SMEM_BYTES>>>(src);
    final_gemm<<<dim3(4, 256), 256>>>(out);
    tanh_kernel<<<16384, 256>>>(out);
}